// round 8
// baseline (speedup 1.0000x reference)
#include <cuda_runtime.h>

// SlidingMean: out = (x - boxfilter_79x69(x)) / 5, SAME (zero) padding.
//  K1: S8[n][g][c] = sum of 8 consecutive rows (4MB, L2-hot; warms L2 with x).
//  K2: fused: vertical 79-tap window init from 9 S8 taps + 7 x rows ->
//      sliding fill into smem -> per-warp register prefix scan ->
//      windowed diff + normalize. No swizzle, 32-bit indexing.

#define HH 512
#define WW 512
#define NB 32
#define KH 79
#define KW 69
#define RH 39   // (KH-1)/2
#define RW 34   // (KW-1)/2
#define TH 16   // output rows per block in K2 (1 row per warp in phase B)
#define NG 64   // 8-row groups per image

__device__ float g_s8[NB * NG * WW];   // 4 MB

// ---------------------------------------------------------------------------
// K1: 8-row group sums. Grid = NB*NG blocks of 512 threads (thread = column).
// ---------------------------------------------------------------------------
__global__ __launch_bounds__(512) void s8_kernel(const float* __restrict__ x) {
    const int blk = blockIdx.x;            // n*NG + g
    const int c = threadIdx.x;
    const float* __restrict__ p = x + (blk << 12) + c;   // blk*8*WW
    float a0 = p[0 * WW] + p[1 * WW];
    float a1 = p[2 * WW] + p[3 * WW];
    float a2 = p[4 * WW] + p[5 * WW];
    float a3 = p[6 * WW] + p[7 * WW];
    g_s8[(blk << 9) + c] = (a0 + a1) + (a2 + a3);
}

__global__ __launch_bounds__(512, 4) void sliding_mean_fused(const float* __restrict__ x,
                                                             float* __restrict__ out) {
    __shared__ float smemC[TH * WW];   // 32 KB, row-major (no swizzle needed)

    const int blk = blockIdx.x;
    const int hc = blk & 31;           // 32 h-chunks of 16 rows
    const int n  = blk >> 5;           // batch
    const int h0 = hc * TH;
    const int t  = threadIdx.x;        // column index in phase A
    const int lane = t & 31;
    const int wrp  = t >> 5;

    const int gbase = n * (HH * WW);
    const float* __restrict__ xp = x + gbase + t;
    const float* __restrict__ s8p = g_s8 + (n << 15) + t;   // n*NG*WW

    // ---- init: window sum over rows [h0-RH, h0+RH] clamped ------------------
    float s;
    const bool interior = (hc >= 3) && (hc <= 28);
    if (interior) {
        // rows h0-39 .. h0-33 (7 rows) + groups (h0-32)/8 .. +8 (9 S8 taps)
        const float* __restrict__ ph = xp + (h0 - 39) * WW;
        float e0 = ph[0 * WW] + ph[1 * WW];
        float e1 = ph[2 * WW] + ph[3 * WW];
        float e2 = ph[4 * WW] + ph[5 * WW];
        float e3 = ph[6 * WW];
        const float* __restrict__ pg = s8p + (((h0 - 32) >> 3) << 9);
        float g0 = pg[0 << 9] + pg[1 << 9];
        float g1 = pg[2 << 9] + pg[3 << 9];
        float g2 = pg[4 << 9] + pg[5 << 9];
        float g3 = pg[6 << 9] + pg[7 << 9];
        float g4 = pg[8 << 9];
        s = ((e0 + e1) + (e2 + e3)) + (((g0 + g1) + (g2 + g3)) + g4);
    } else {
        int lo = h0 - RH; if (lo < 0) lo = 0;
        int hi = h0 + RH; if (hi > HH - 1) hi = HH - 1;
        const int glo = (lo + 7) >> 3;
        const int ghi = (hi + 1) >> 3;
        float s0 = 0.f, s1 = 0.f;
        for (int r = lo; r < (glo << 3); ++r) s0 += xp[r * WW];
        int g = glo;
        for (; g + 1 < ghi; g += 2) {
            s0 += s8p[g << 9];
            s1 += s8p[(g + 1) << 9];
        }
        if (g < ghi) s0 += s8p[g << 9];
        for (int r = (ghi << 3); r <= hi; ++r) s1 += xp[r * WW];
        s = s0 + s1;
    }

    // ---- phase A: sliding fill of 16 colsum rows into smem ------------------
    if (interior) {
        const float* __restrict__ pa = xp + (h0 + RH + 1) * WW;
        const float* __restrict__ pb = xp + (h0 - RH) * WW;
        #pragma unroll
        for (int k = 0; k < TH; ++k) {
            smemC[(k << 9) + t] = s;
            s += pa[k * WW] - pb[k * WW];
        }
    } else {
        #pragma unroll
        for (int k = 0; k < TH; ++k) {
            smemC[(k << 9) + t] = s;
            int add = h0 + k + RH + 1;
            int sb  = h0 + k - RH;
            float a = (add < HH) ? xp[add * WW] : 0.f;
            float b = (sb >= 0)  ? xp[sb * WW]  : 0.f;
            s += a - b;
        }
    }
    __syncthreads();

    // ---- phase B: per-warp row prefix scan in registers ---------------------
    const unsigned FULL = 0xffffffffu;
    float* __restrict__ row = smemC + (wrp << 9);

    float p[16];
    #pragma unroll
    for (int c = 0; c < 4; ++c) {
        float4 v = *reinterpret_cast<const float4*>(row + (lane << 4) + (c << 2));
        p[c * 4 + 0] = v.x; p[c * 4 + 1] = v.y; p[c * 4 + 2] = v.z; p[c * 4 + 3] = v.w;
    }
    #pragma unroll
    for (int j = 1; j < 16; ++j) p[j] += p[j - 1];
    float tot = p[15];
    float inc = tot;
    #pragma unroll
    for (int off = 1; off < 32; off <<= 1) {
        float u = __shfl_up_sync(FULL, inc, off);
        if (lane >= off) inc += u;
    }
    float excl = inc - tot;
    #pragma unroll
    for (int j = 0; j < 16; ++j) p[j] += excl;
    #pragma unroll
    for (int c = 0; c < 4; ++c) {
        *reinterpret_cast<float4*>(row + (lane << 4) + (c << 2)) =
            make_float4(p[c * 4 + 0], p[c * 4 + 1], p[c * 4 + 2], p[c * 4 + 3]);
    }
    __syncwarp();  // only this warp touches this row

    // ---- epilogue: window diff + normalize (coalesced) ----------------------
    const float inv_cnt = 1.0f / (float)(KH * KW);
    const float inv_std = 0.2f;  // 1/5
    const int rbase = gbase + (h0 + wrp) * WW;
    #pragma unroll
    for (int i = 0; i < 16; ++i) {
        int w = lane + (i << 5);
        int hiI = w + RW; if (hiI > WW - 1) hiI = WW - 1;
        int loI = w - RW - 1;
        float hiv = row[hiI];
        float lov = (loI >= 0) ? row[loI] : 0.0f;
        float winsum = hiv - lov;
        int o = rbase + w;
        float r = (x[o] - winsum * inv_cnt) * inv_std;
        __stcs(&out[o], r);   // streaming store: keep x hot in L2
    }
}

extern "C" void kernel_launch(void* const* d_in, const int* in_sizes, int n_in,
                              void* d_out, int out_size) {
    const float* x = (const float*)d_in[0];
    float* out = (float*)d_out;

    s8_kernel<<<NB * NG, 512>>>(x);
    sliding_mean_fused<<<NB * (HH / TH), 512>>>(x, out);
}

// round 9
// speedup vs baseline: 1.2347x; 1.2347x over previous
#include <cuda_runtime.h>

// SlidingMean: out = (x - boxfilter_79x69(x)) / 5, SAME (zero) padding.
//  K1: S8[n][g][c] = sum of 8 consecutive rows (4MB, L2-hot; warms L2 with x).
//  K2: fused: vertical 79-tap window init from 9 S8 taps + 7 x rows ->
//      sliding fill into plain smem -> per-warp block-cyclic register prefix
//      scan (conflict-free, no swizzle) -> windowed diff + normalize.

#define HH 512
#define WW 512
#define NB 32
#define KH 79
#define KW 69
#define RH 39   // (KH-1)/2
#define RW 34   // (KW-1)/2
#define TH 16   // output rows per block in K2 (1 row per warp in phase B)
#define NG 64   // 8-row groups per image

__device__ float g_s8[NB * NG * WW];   // 4 MB

// ---------------------------------------------------------------------------
// K1: 8-row group sums. Grid = NB*NG blocks of 512 threads (thread = column).
// ---------------------------------------------------------------------------
__global__ __launch_bounds__(512) void s8_kernel(const float* __restrict__ x) {
    const int blk = blockIdx.x;            // n*NG + g
    const int c = threadIdx.x;
    const float* __restrict__ p = x + (blk << 12) + c;   // blk*8*WW
    float a0 = p[0 * WW] + p[1 * WW];
    float a1 = p[2 * WW] + p[3 * WW];
    float a2 = p[4 * WW] + p[5 * WW];
    float a3 = p[6 * WW] + p[7 * WW];
    g_s8[(blk << 9) + c] = (a0 + a1) + (a2 + a3);
}

__global__ __launch_bounds__(512, 4) void sliding_mean_fused(const float* __restrict__ x,
                                                             float* __restrict__ out) {
    __shared__ float smemC[TH * WW];   // 32 KB, plain row-major

    const int blk = blockIdx.x;
    const int hc = blk & 31;           // 32 h-chunks of 16 rows
    const int n  = blk >> 5;           // batch
    const int h0 = hc * TH;
    const int t  = threadIdx.x;        // column index in phase A
    const int lane = t & 31;
    const int wrp  = t >> 5;

    const int gbase = n * (HH * WW);
    const float* __restrict__ xp = x + gbase + t;
    const float* __restrict__ s8p = g_s8 + (n << 15) + t;   // n*NG*WW

    // ---- init: window sum over rows [h0-RH, h0+RH] clamped ------------------
    float s;
    const bool interior = (hc >= 3) && (hc <= 28);
    if (interior) {
        // rows h0-39 .. h0-33 (7 rows) + groups (h0-32)/8 .. +8 (9 S8 taps)
        const float* __restrict__ ph = xp + (h0 - 39) * WW;
        float e0 = ph[0 * WW] + ph[1 * WW];
        float e1 = ph[2 * WW] + ph[3 * WW];
        float e2 = ph[4 * WW] + ph[5 * WW];
        float e3 = ph[6 * WW];
        const float* __restrict__ pg = s8p + (((h0 - 32) >> 3) << 9);
        float g0 = pg[0 << 9] + pg[1 << 9];
        float g1 = pg[2 << 9] + pg[3 << 9];
        float g2 = pg[4 << 9] + pg[5 << 9];
        float g3 = pg[6 << 9] + pg[7 << 9];
        float g4 = pg[8 << 9];
        s = ((e0 + e1) + (e2 + e3)) + (((g0 + g1) + (g2 + g3)) + g4);
    } else {
        int lo = h0 - RH; if (lo < 0) lo = 0;
        int hi = h0 + RH; if (hi > HH - 1) hi = HH - 1;
        const int glo = (lo + 7) >> 3;
        const int ghi = (hi + 1) >> 3;
        float s0 = 0.f, s1 = 0.f;
        for (int r = lo; r < (glo << 3); ++r) s0 += xp[r * WW];
        int g = glo;
        for (; g + 1 < ghi; g += 2) {
            s0 += s8p[g << 9];
            s1 += s8p[(g + 1) << 9];
        }
        if (g < ghi) s0 += s8p[g << 9];
        for (int r = (ghi << 3); r <= hi; ++r) s1 += xp[r * WW];
        s = s0 + s1;
    }

    // ---- phase A: sliding fill of 16 colsum rows into smem ------------------
    if (interior) {
        const float* __restrict__ pa = xp + (h0 + RH + 1) * WW;
        const float* __restrict__ pb = xp + (h0 - RH) * WW;
        #pragma unroll
        for (int k = 0; k < TH; ++k) {
            smemC[(k << 9) + t] = s;
            s += pa[k * WW] - pb[k * WW];
        }
    } else {
        #pragma unroll
        for (int k = 0; k < TH; ++k) {
            smemC[(k << 9) + t] = s;
            int add = h0 + k + RH + 1;
            int sb  = h0 + k - RH;
            float a = (add < HH) ? xp[add * WW] : 0.f;
            float b = (sb >= 0)  ? xp[sb * WW]  : 0.f;
            s += a - b;
        }
    }
    __syncthreads();

    // ---- phase B: per-warp block-cyclic prefix scan (conflict-free) ---------
    // lane holds elements [128c + 4*lane, 128c + 4*lane + 4), c = 0..3.
    // float4 index lane + 32c -> 16B lane stride -> no bank conflicts.
    const unsigned FULL = 0xffffffffu;
    float* __restrict__ row = smemC + (wrp << 9);
    float4* __restrict__ row4 = reinterpret_cast<float4*>(row);

    float p[16];
    #pragma unroll
    for (int c = 0; c < 4; ++c) {
        float4 v = row4[lane + (c << 5)];
        p[c * 4 + 0] = v.x; p[c * 4 + 1] = v.y; p[c * 4 + 2] = v.z; p[c * 4 + 3] = v.w;
    }
    // local prefix within each 4-chunk
    #pragma unroll
    for (int c = 0; c < 4; ++c) {
        p[c * 4 + 1] += p[c * 4 + 0];
        p[c * 4 + 2] += p[c * 4 + 1];
        p[c * 4 + 3] += p[c * 4 + 2];
    }
    // 4 independent warp scans of the chunk totals
    float tot0 = p[3], tot1 = p[7], tot2 = p[11], tot3 = p[15];
    float i0 = tot0, i1 = tot1, i2 = tot2, i3 = tot3;
    #pragma unroll
    for (int off = 1; off < 32; off <<= 1) {
        float u0 = __shfl_up_sync(FULL, i0, off);
        float u1 = __shfl_up_sync(FULL, i1, off);
        float u2 = __shfl_up_sync(FULL, i2, off);
        float u3 = __shfl_up_sync(FULL, i3, off);
        if (lane >= off) { i0 += u0; i1 += u1; i2 += u2; i3 += u3; }
    }
    // block totals (sum over all lanes of each 128-block)
    float B0 = __shfl_sync(FULL, i0, 31);
    float B1 = __shfl_sync(FULL, i1, 31);
    float B2 = __shfl_sync(FULL, i2, 31);
    // exclusive offsets per chunk
    float o0 = i0 - tot0;
    float o1 = i1 - tot1 + B0;
    float o2 = i2 - tot2 + (B0 + B1);
    float o3 = i3 - tot3 + ((B0 + B1) + B2);
    p[0] += o0;  p[1] += o0;  p[2] += o0;  p[3] += o0;
    p[4] += o1;  p[5] += o1;  p[6] += o1;  p[7] += o1;
    p[8] += o2;  p[9] += o2;  p[10] += o2; p[11] += o2;
    p[12] += o3; p[13] += o3; p[14] += o3; p[15] += o3;
    // store prefix back (same conflict-free addresses)
    #pragma unroll
    for (int c = 0; c < 4; ++c) {
        row4[lane + (c << 5)] =
            make_float4(p[c * 4 + 0], p[c * 4 + 1], p[c * 4 + 2], p[c * 4 + 3]);
    }
    __syncwarp();  // only this warp touches this row

    // ---- epilogue: window diff + normalize (coalesced, conflict-free taps) --
    const float inv_cnt = 1.0f / (float)(KH * KW);
    const float inv_std = 0.2f;  // 1/5
    const int rbase = gbase + (h0 + wrp) * WW;
    #pragma unroll
    for (int i = 0; i < 16; ++i) {
        int w = lane + (i << 5);
        int hiI = w + RW; if (hiI > WW - 1) hiI = WW - 1;
        int loI = w - RW - 1;
        float hiv = row[hiI];
        float lov = (loI >= 0) ? row[loI] : 0.0f;
        float winsum = hiv - lov;
        int o = rbase + w;
        float r = (x[o] - winsum * inv_cnt) * inv_std;
        __stcs(&out[o], r);   // streaming store: keep x hot in L2
    }
}

extern "C" void kernel_launch(void* const* d_in, const int* in_sizes, int n_in,
                              void* d_out, int out_size) {
    const float* x = (const float*)d_in[0];
    float* out = (float*)d_out;

    s8_kernel<<<NB * NG, 512>>>(x);
    sliding_mean_fused<<<NB * (HH / TH), 512>>>(x, out);
}

// round 10
// speedup vs baseline: 1.2364x; 1.0014x over previous
#include <cuda_runtime.h>

// SlidingMean: out = (x - boxfilter_79x69(x)) / 5, SAME (zero) padding.
//  K1: S8[n][g][c] = sum of 8 consecutive rows (4MB, L2-hot; warms L2 with x).
//  K2: fused. Phase A: two independent 8-row halves per block, float2 columns
//      (half the instructions, half the serial carry). Init from 9 S8 taps +
//      7 x rows. Phase B: per-warp block-cyclic register prefix scan
//      (conflict-free). Epilogue: windowed diff + normalize (coalesced).

#define HH 512
#define WW 512
#define NB 32
#define KH 79
#define KW 69
#define RH 39   // (KH-1)/2
#define RW 34   // (KW-1)/2
#define TH 16   // output rows per block in K2 (1 row per warp in phase B)
#define NG 64   // 8-row groups per image

__device__ float g_s8[NB * NG * WW];   // 4 MB

// ---------------------------------------------------------------------------
// K1: 8-row group sums. Grid = NB*NG blocks of 512 threads (thread = column).
// ---------------------------------------------------------------------------
__global__ __launch_bounds__(512) void s8_kernel(const float* __restrict__ x) {
    const int blk = blockIdx.x;            // n*NG + g
    const int c = threadIdx.x;
    const float* __restrict__ p = x + (blk << 12) + c;   // blk*8*WW
    float a0 = p[0 * WW] + p[1 * WW];
    float a1 = p[2 * WW] + p[3 * WW];
    float a2 = p[4 * WW] + p[5 * WW];
    float a3 = p[6 * WW] + p[7 * WW];
    g_s8[(blk << 9) + c] = (a0 + a1) + (a2 + a3);
}

__device__ __forceinline__ float2 f2add(float2 a, float2 b) {
    return make_float2(a.x + b.x, a.y + b.y);
}
__device__ __forceinline__ float2 f2sub(float2 a, float2 b) {
    return make_float2(a.x - b.x, a.y - b.y);
}

__global__ __launch_bounds__(512, 4) void sliding_mean_fused(const float* __restrict__ x,
                                                             float* __restrict__ out) {
    __shared__ float smemC[TH * WW];   // 32 KB, plain row-major

    const int blk = blockIdx.x;
    const int hc = blk & 31;           // 32 h-chunks of 16 rows
    const int n  = blk >> 5;           // batch
    const int h0 = hc * TH;
    const int t  = threadIdx.x;
    const int lane = t & 31;
    const int wrp  = t >> 5;

    const int gbase = n * (HH * WW);

    // ======================= Phase A (float2, two halves) ====================
    {
        const int halfid = t >> 8;         // 0: rows 0-7, 1: rows 8-15
        const int ht = t & 255;            // column-pair index (col = 2*ht)
        const int hb = h0 + (halfid << 3); // first row of this half

        const float2* __restrict__ xp2 =
            reinterpret_cast<const float2*>(x + gbase) + ht;          // row stride 256
        const float2* __restrict__ s8p2 =
            reinterpret_cast<const float2*>(g_s8 + (n << 15)) + ht;   // group stride 256
        float2* __restrict__ sm2 =
            reinterpret_cast<float2*>(smemC) + (halfid << 11) + ht;   // 8 rows * 256

        float2 s;
        const bool interior = (hb >= 40) && (hb <= 464);
        if (interior) {
            // rows hb-39..hb-33 (7) + S8 groups (hb-32)/8 .. +8 (9 taps)
            const float2* __restrict__ ph = xp2 + ((hb - 39) << 8);
            float2 e0 = f2add(ph[0 << 8], ph[1 << 8]);
            float2 e1 = f2add(ph[2 << 8], ph[3 << 8]);
            float2 e2 = f2add(ph[4 << 8], ph[5 << 8]);
            float2 e3 = ph[6 << 8];
            const float2* __restrict__ pg = s8p2 + (((hb - 32) >> 3) << 8);
            float2 g0 = f2add(pg[0 << 8], pg[1 << 8]);
            float2 g1 = f2add(pg[2 << 8], pg[3 << 8]);
            float2 g2 = f2add(pg[4 << 8], pg[5 << 8]);
            float2 g3 = f2add(pg[6 << 8], pg[7 << 8]);
            float2 g4 = pg[8 << 8];
            s = f2add(f2add(f2add(e0, e1), f2add(e2, e3)),
                      f2add(f2add(f2add(g0, g1), f2add(g2, g3)), g4));

            const float2* __restrict__ pa = xp2 + ((hb + RH + 1) << 8);
            const float2* __restrict__ pb = xp2 + ((hb - RH) << 8);
            #pragma unroll
            for (int k = 0; k < 8; ++k) {
                sm2[k << 8] = s;
                s = f2add(s, f2sub(pa[k << 8], pb[k << 8]));
            }
        } else {
            int lo = hb - RH; if (lo < 0) lo = 0;
            int hi = hb + RH; if (hi > HH - 1) hi = HH - 1;
            const int glo = (lo + 7) >> 3;
            const int ghi = (hi + 1) >> 3;
            s = make_float2(0.f, 0.f);
            for (int r = lo; r < (glo << 3); ++r) s = f2add(s, xp2[r << 8]);
            for (int g = glo; g < ghi; ++g)       s = f2add(s, s8p2[g << 8]);
            for (int r = (ghi << 3); r <= hi; ++r) s = f2add(s, xp2[r << 8]);

            #pragma unroll
            for (int k = 0; k < 8; ++k) {
                sm2[k << 8] = s;
                int add = hb + k + RH + 1;
                int sb  = hb + k - RH;
                float2 a = (add < HH) ? xp2[add << 8] : make_float2(0.f, 0.f);
                float2 b = (sb >= 0)  ? xp2[sb << 8]  : make_float2(0.f, 0.f);
                s = f2add(s, f2sub(a, b));
            }
        }
    }
    __syncthreads();

    // ========== Phase B: per-warp block-cyclic prefix scan (conflict-free) ===
    const unsigned FULL = 0xffffffffu;
    float* __restrict__ row = smemC + (wrp << 9);
    float4* __restrict__ row4 = reinterpret_cast<float4*>(row);

    float p[16];
    #pragma unroll
    for (int c = 0; c < 4; ++c) {
        float4 v = row4[lane + (c << 5)];
        p[c * 4 + 0] = v.x; p[c * 4 + 1] = v.y; p[c * 4 + 2] = v.z; p[c * 4 + 3] = v.w;
    }
    #pragma unroll
    for (int c = 0; c < 4; ++c) {
        p[c * 4 + 1] += p[c * 4 + 0];
        p[c * 4 + 2] += p[c * 4 + 1];
        p[c * 4 + 3] += p[c * 4 + 2];
    }
    float tot0 = p[3], tot1 = p[7], tot2 = p[11], tot3 = p[15];
    float i0 = tot0, i1 = tot1, i2 = tot2, i3 = tot3;
    #pragma unroll
    for (int off = 1; off < 32; off <<= 1) {
        float u0 = __shfl_up_sync(FULL, i0, off);
        float u1 = __shfl_up_sync(FULL, i1, off);
        float u2 = __shfl_up_sync(FULL, i2, off);
        float u3 = __shfl_up_sync(FULL, i3, off);
        if (lane >= off) { i0 += u0; i1 += u1; i2 += u2; i3 += u3; }
    }
    float B0 = __shfl_sync(FULL, i0, 31);
    float B1 = __shfl_sync(FULL, i1, 31);
    float B2 = __shfl_sync(FULL, i2, 31);
    float o0 = i0 - tot0;
    float o1 = i1 - tot1 + B0;
    float o2 = i2 - tot2 + (B0 + B1);
    float o3 = i3 - tot3 + ((B0 + B1) + B2);
    p[0] += o0;  p[1] += o0;  p[2] += o0;  p[3] += o0;
    p[4] += o1;  p[5] += o1;  p[6] += o1;  p[7] += o1;
    p[8] += o2;  p[9] += o2;  p[10] += o2; p[11] += o2;
    p[12] += o3; p[13] += o3; p[14] += o3; p[15] += o3;
    #pragma unroll
    for (int c = 0; c < 4; ++c) {
        row4[lane + (c << 5)] =
            make_float4(p[c * 4 + 0], p[c * 4 + 1], p[c * 4 + 2], p[c * 4 + 3]);
    }
    __syncwarp();  // only this warp touches this row

    // ============== Epilogue: window diff + normalize (coalesced) ============
    const float inv_cnt = 1.0f / (float)(KH * KW);
    const float inv_std = 0.2f;  // 1/5
    const int rbase = gbase + (h0 + wrp) * WW;
    #pragma unroll
    for (int i = 0; i < 16; ++i) {
        int w = lane + (i << 5);
        int hiI = w + RW; if (hiI > WW - 1) hiI = WW - 1;
        int loI = w - RW - 1;
        float hiv = row[hiI];
        float lov = (loI >= 0) ? row[loI] : 0.0f;
        float winsum = hiv - lov;
        int o = rbase + w;
        float r = (x[o] - winsum * inv_cnt) * inv_std;
        __stcs(&out[o], r);   // streaming store: keep x hot in L2
    }
}

extern "C" void kernel_launch(void* const* d_in, const int* in_sizes, int n_in,
                              void* d_out, int out_size) {
    const float* x = (const float*)d_in[0];
    float* out = (float*)d_out;

    s8_kernel<<<NB * NG, 512>>>(x);
    sliding_mean_fused<<<NB * (HH / TH), 512>>>(x, out);
}